// round 8
// baseline (speedup 1.0000x reference)
#include <cuda_runtime.h>
#include <math.h>

#define BATCH 256
#define NF 512
#define DM 1024
#define DH 512
#define KH 16          // Fourier harmonics for |cos|
#define ZP 8           // split-K factor for phi
#define ZC 4           // split-K factor for coupled/gate
#define GRID 256

// -------- scratch --------
__device__ float g_php[ZP][BATCH * DM];   // phi split-K partials
__device__ float g_phi[BATCH * DM];
__device__ float g_ca[BATCH * DM];
__device__ float g_cp[ZC][BATCH * DM];    // coupled split-K partials
__device__ float g_gt[ZC][BATCH * DH];    // gate pre-act split-K partials
__device__ unsigned g_cnt[4];             // grid barrier counters (monotonic)

typedef unsigned long long u64;

__device__ __forceinline__ u64 f32x2_fma(u64 a, u64 b, u64 c) {
    u64 d;
    asm("fma.rn.f32x2 %0, %1, %2, %3;" : "=l"(d) : "l"(a), "l"(b), "l"(c));
    return d;
}
__device__ __forceinline__ u64 pack_dup(float v) {
    u64 r;
    asm("mov.b64 %0, {%1, %2};" : "=l"(r) : "f"(v), "f"(v));
    return r;
}
__device__ __forceinline__ float2 unpack2(u64 v) {
    float lo, hi;
    asm("mov.b64 {%0, %1}, %2;" : "=f"(lo), "=f"(hi) : "l"(v));
    return make_float2(lo, hi);
}

// Monotonic grid barrier: counter only ever increments; each use advances
// to the next multiple of GRID. Replay-safe (no reset), single wave
// co-residency guaranteed by launch_bounds + grid size.
__device__ __forceinline__ void grid_bar(int k) {
    __syncthreads();
    if (threadIdx.x == 0) {
        __threadfence();
        unsigned old = atomicAdd(&g_cnt[k], 1u);
        unsigned target = (old / GRID + 1u) * GRID;
        while (*((volatile unsigned*)&g_cnt[k]) < target) { }
        __threadfence();
    }
    __syncthreads();
}

// ============================================================
// Persistent fused kernel: 256 blocks x 256 threads.
// Phase 0: phi partial GEMMs (512 half-block groups, 8x4 tile)
// Phase 1: phi combine + Fourier coherence + ca
// Phase 2: coupled/gate partial GEMMs (384 groups) + W copy (64 blocks)
// Phase 3: LayerNorm epilogue
// ============================================================
__global__ __launch_bounds__(256, 2) void fused_kernel(
    const float* __restrict__ x, const float* __restrict__ prev_ca,
    const float* __restrict__ Wp, const float* __restrict__ bp,
    const float* __restrict__ Wg, const float* __restrict__ bg,
    const float* __restrict__ W, const float* __restrict__ gamma,
    const float* __restrict__ beta,
    float* __restrict__ out_feat, float* __restrict__ out_ca,
    float* __restrict__ out_W)
{
    __shared__ union {
        struct { u64 As[16][64]; float Bs[16][64]; } g[2];           // 24.6KB
        struct { float red[2 * KH][257]; float C[KH]; float S[KH]; } ca; // 33KB
        struct { float s1[8]; float s2[8]; } ln;
    } sm;

    const int tid = threadIdx.x;
    const int half = tid >> 7;          // 0/1: 128-thread group in block
    const int t = tid & 127;

    // ================= Phase 0: phi = x @ Wp^T (split-K x8) =================
    {
        const int g = blockIdx.x * 2 + half;       // 0..511
        const int z = g >> 6;                      // 0..7
        const int idx = g & 63;
        const int bm = (idx >> 4) * 64;            // 0..192
        const int bn = (idx & 15) * 64;            // 0..960
        const int ty = t >> 4, tx = t & 15;
        const int ry = ty * 8, cx = tx * 4;
        const int arow = t >> 1, akh = (t & 1) * 8;
        const int kbeg = z * (NF / ZP);            // 64-wide K slice

        u64 (*As)[64] = sm.g[half].As;
        float (*Bs)[64] = sm.g[half].Bs;

        u64 acc[8][2];
#pragma unroll
        for (int r = 0; r < 8; r++) { acc[r][0] = 0ull; acc[r][1] = 0ull; }

        for (int k0 = kbeg; k0 < kbeg + NF / ZP; k0 += 16) {
            {
                const float* src = x + (size_t)(bm + arow) * NF + k0 + akh;
                float4 v0 = *(const float4*)(src);
                float4 v1 = *(const float4*)(src + 4);
                As[akh + 0][arow] = pack_dup(v0.x); As[akh + 1][arow] = pack_dup(v0.y);
                As[akh + 2][arow] = pack_dup(v0.z); As[akh + 3][arow] = pack_dup(v0.w);
                As[akh + 4][arow] = pack_dup(v1.x); As[akh + 5][arow] = pack_dup(v1.y);
                As[akh + 6][arow] = pack_dup(v1.z); As[akh + 7][arow] = pack_dup(v1.w);
            }
            {
                const float* src = Wp + (size_t)(bn + arow) * NF + k0 + akh;
                float4 v0 = *(const float4*)(src);
                float4 v1 = *(const float4*)(src + 4);
                Bs[akh + 0][arow] = v0.x; Bs[akh + 1][arow] = v0.y;
                Bs[akh + 2][arow] = v0.z; Bs[akh + 3][arow] = v0.w;
                Bs[akh + 4][arow] = v1.x; Bs[akh + 5][arow] = v1.y;
                Bs[akh + 6][arow] = v1.z; Bs[akh + 7][arow] = v1.w;
            }
            __syncthreads();   // both halves: identical trip counts

#pragma unroll
            for (int k = 0; k < 16; k++) {
                ulonglong2 a01 = *(const ulonglong2*)&As[k][ry];
                ulonglong2 a23 = *(const ulonglong2*)&As[k][ry + 2];
                ulonglong2 a45 = *(const ulonglong2*)&As[k][ry + 4];
                ulonglong2 a67 = *(const ulonglong2*)&As[k][ry + 6];
                double2 bd = *(const double2*)&Bs[k][cx];
                u64 b0 = __double_as_longlong(bd.x);
                u64 b1 = __double_as_longlong(bd.y);
                acc[0][0] = f32x2_fma(a01.x, b0, acc[0][0]);
                acc[0][1] = f32x2_fma(a01.x, b1, acc[0][1]);
                acc[1][0] = f32x2_fma(a01.y, b0, acc[1][0]);
                acc[1][1] = f32x2_fma(a01.y, b1, acc[1][1]);
                acc[2][0] = f32x2_fma(a23.x, b0, acc[2][0]);
                acc[2][1] = f32x2_fma(a23.x, b1, acc[2][1]);
                acc[3][0] = f32x2_fma(a23.y, b0, acc[3][0]);
                acc[3][1] = f32x2_fma(a23.y, b1, acc[3][1]);
                acc[4][0] = f32x2_fma(a45.x, b0, acc[4][0]);
                acc[4][1] = f32x2_fma(a45.x, b1, acc[4][1]);
                acc[5][0] = f32x2_fma(a45.y, b0, acc[5][0]);
                acc[5][1] = f32x2_fma(a45.y, b1, acc[5][1]);
                acc[6][0] = f32x2_fma(a67.x, b0, acc[6][0]);
                acc[6][1] = f32x2_fma(a67.x, b1, acc[6][1]);
                acc[7][0] = f32x2_fma(a67.y, b0, acc[7][0]);
                acc[7][1] = f32x2_fma(a67.y, b1, acc[7][1]);
            }
            __syncthreads();
        }

        const int gn0 = bn + cx;
#pragma unroll
        for (int r = 0; r < 8; r++) {
            float2 lo = unpack2(acc[r][0]);
            float2 hi = unpack2(acc[r][1]);
            *(float4*)(&g_php[z][(size_t)(bm + ry + r) * DM + gn0]) =
                make_float4(lo.x, lo.y, hi.x, hi.y);
        }
    }
    grid_bar(0);

    // ================= Phase 1: ca (Fourier coherence) =================
    {
        const int b = blockIdx.x;
        const int warp = tid >> 5, lane = tid & 31;
        const int j0 = tid * 4;

        float4 bb = *(const float4*)(bp + j0);
        float phi[4] = { bb.x, bb.y, bb.z, bb.w };
#pragma unroll
        for (int zz = 0; zz < ZP; zz++) {
            float4 p = *(const float4*)(&g_php[zz][(size_t)b * DM + j0]);
            phi[0] += p.x; phi[1] += p.y; phi[2] += p.z; phi[3] += p.w;
        }
        *(float4*)(&g_phi[(size_t)b * DM + j0]) =
            make_float4(phi[0], phi[1], phi[2], phi[3]);

        float c1[4], s1[4], tt[4], ck[4], sk[4], cm[4], smv[4];
#pragma unroll
        for (int q = 0; q < 4; q++) {
            sincosf(2.0f * phi[q], &s1[q], &c1[q]);
            tt[q] = 2.0f * c1[q];
            ck[q] = c1[q]; sk[q] = s1[q];
            cm[q] = 1.0f;  smv[q] = 0.0f;
        }

#pragma unroll
        for (int k = 0; k < KH; k++) {
            sm.ca.red[k][tid]      = ck[0] + ck[1] + ck[2] + ck[3];
            sm.ca.red[k + KH][tid] = sk[0] + sk[1] + sk[2] + sk[3];
#pragma unroll
            for (int q = 0; q < 4; q++) {
                float cn = fmaf(tt[q], ck[q], -cm[q]);
                float sn = fmaf(tt[q], sk[q], -smv[q]);
                cm[q] = ck[q]; ck[q] = cn;
                smv[q] = sk[q]; sk[q] = sn;
            }
        }
        __syncthreads();

#pragma unroll
        for (int h = 0; h < 4; h++) {
            int hh = warp * 4 + h;
            float v = sm.ca.red[hh][lane] + sm.ca.red[hh][lane + 32] +
                      sm.ca.red[hh][lane + 64] + sm.ca.red[hh][lane + 96] +
                      sm.ca.red[hh][lane + 128] + sm.ca.red[hh][lane + 160] +
                      sm.ca.red[hh][lane + 192] + sm.ca.red[hh][lane + 224];
#pragma unroll
            for (int o = 16; o > 0; o >>= 1)
                v += __shfl_xor_sync(0xFFFFFFFFu, v, o);
            if (lane == 0) {
                int m = (hh & (KH - 1)) + 1;
                float coef = ((m & 1) ? 1.0f : -1.0f) *
                             (4.0f / 3.14159265358979f) / (float)(4 * m * m - 1) *
                             (1.0f / (float)DM);
                if (hh < KH) sm.ca.C[hh] = v * coef;
                else         sm.ca.S[hh - KH] = v * coef;
            }
        }
        __syncthreads();

        float acc[4] = { 0.63661977f, 0.63661977f, 0.63661977f, 0.63661977f };
#pragma unroll
        for (int q = 0; q < 4; q++) {
            ck[q] = c1[q]; sk[q] = s1[q];
            cm[q] = 1.0f;  smv[q] = 0.0f;
        }
#pragma unroll
        for (int k = 0; k < KH; k++) {
            float C = sm.ca.C[k], S = sm.ca.S[k];
#pragma unroll
            for (int q = 0; q < 4; q++) {
                acc[q] = fmaf(ck[q], C, acc[q]);
                acc[q] = fmaf(sk[q], S, acc[q]);
                float cn = fmaf(tt[q], ck[q], -cm[q]);
                float sn = fmaf(tt[q], sk[q], -smv[q]);
                cm[q] = ck[q]; ck[q] = cn;
                smv[q] = sk[q]; sk[q] = sn;
            }
        }

        float4 pc = *(const float4*)(prev_ca + (size_t)b * DM + j0);
        float4 ca;
        ca.x = pc.x * 0.95f + acc[0] * 0.05f;
        ca.y = pc.y * 0.95f + acc[1] * 0.05f;
        ca.z = pc.z * 0.95f + acc[2] * 0.05f;
        ca.w = pc.w * 0.95f + acc[3] * 0.05f;
        *(float4*)(&g_ca[(size_t)b * DM + j0]) = ca;
        if (out_ca) *(float4*)(out_ca + (size_t)b * DM + j0) = ca;
    }
    grid_bar(1);

    // ========== Phase 2: coupled/gate GEMM (blocks<192) or W copy ==========
    if (blockIdx.x < 192) {
        const int g = blockIdx.x * 2 + half;       // 0..383
        const int bx = g % 24;
        const int q24 = g / 24;                    // 0..15
        const int bm = (q24 & 3) * 64;
        const int z = q24 >> 2;                    // 0..3
        const bool is_gate = (bx >= 16);
        const int bn = (is_gate ? (bx - 16) : bx) * 64;
        const int ty = t >> 4, tx = t & 15;
        const int ry = ty * 8, cx = tx * 4;
        const int arow = t >> 1, akh = (t & 1) * 8;
        const int kbeg = z * (DM / ZC);

        const float* Ap = is_gate ? (const float*)g_ca : (const float*)g_phi;
        u64 (*As)[64] = sm.g[half].As;
        float (*Bs)[64] = sm.g[half].Bs;

        u64 acc[8][2];
#pragma unroll
        for (int r = 0; r < 8; r++) { acc[r][0] = 0ull; acc[r][1] = 0ull; }

        for (int k0 = kbeg; k0 < kbeg + DM / ZC; k0 += 16) {
            {
                const float* src = Ap + (size_t)(bm + arow) * DM + k0 + akh;
                float4 v0 = *(const float4*)(src);
                float4 v1 = *(const float4*)(src + 4);
                As[akh + 0][arow] = pack_dup(v0.x); As[akh + 1][arow] = pack_dup(v0.y);
                As[akh + 2][arow] = pack_dup(v0.z); As[akh + 3][arow] = pack_dup(v0.w);
                As[akh + 4][arow] = pack_dup(v1.x); As[akh + 5][arow] = pack_dup(v1.y);
                As[akh + 6][arow] = pack_dup(v1.z); As[akh + 7][arow] = pack_dup(v1.w);
            }
            if (is_gate) {
                const float* src = Wg + (size_t)(bn + arow) * DM + k0 + akh;
                float4 v0 = *(const float4*)(src);
                float4 v1 = *(const float4*)(src + 4);
                Bs[akh + 0][arow] = v0.x; Bs[akh + 1][arow] = v0.y;
                Bs[akh + 2][arow] = v0.z; Bs[akh + 3][arow] = v0.w;
                Bs[akh + 4][arow] = v1.x; Bs[akh + 5][arow] = v1.y;
                Bs[akh + 6][arow] = v1.z; Bs[akh + 7][arow] = v1.w;
            } else {
                int kr = t >> 3, nc = (t & 7) << 3;
                const float* src = W + (size_t)(k0 + kr) * DM + bn + nc;
                *(float4*)&Bs[kr][nc]     = *(const float4*)(src);
                *(float4*)&Bs[kr][nc + 4] = *(const float4*)(src + 4);
            }
            __syncthreads();

#pragma unroll
            for (int k = 0; k < 16; k++) {
                ulonglong2 a01 = *(const ulonglong2*)&As[k][ry];
                ulonglong2 a23 = *(const ulonglong2*)&As[k][ry + 2];
                ulonglong2 a45 = *(const ulonglong2*)&As[k][ry + 4];
                ulonglong2 a67 = *(const ulonglong2*)&As[k][ry + 6];
                double2 bd = *(const double2*)&Bs[k][cx];
                u64 b0 = __double_as_longlong(bd.x);
                u64 b1 = __double_as_longlong(bd.y);
                acc[0][0] = f32x2_fma(a01.x, b0, acc[0][0]);
                acc[0][1] = f32x2_fma(a01.x, b1, acc[0][1]);
                acc[1][0] = f32x2_fma(a01.y, b0, acc[1][0]);
                acc[1][1] = f32x2_fma(a01.y, b1, acc[1][1]);
                acc[2][0] = f32x2_fma(a23.x, b0, acc[2][0]);
                acc[2][1] = f32x2_fma(a23.x, b1, acc[2][1]);
                acc[3][0] = f32x2_fma(a23.y, b0, acc[3][0]);
                acc[3][1] = f32x2_fma(a23.y, b1, acc[3][1]);
                acc[4][0] = f32x2_fma(a45.x, b0, acc[4][0]);
                acc[4][1] = f32x2_fma(a45.x, b1, acc[4][1]);
                acc[5][0] = f32x2_fma(a45.y, b0, acc[5][0]);
                acc[5][1] = f32x2_fma(a45.y, b1, acc[5][1]);
                acc[6][0] = f32x2_fma(a67.x, b0, acc[6][0]);
                acc[6][1] = f32x2_fma(a67.x, b1, acc[6][1]);
                acc[7][0] = f32x2_fma(a67.y, b0, acc[7][0]);
                acc[7][1] = f32x2_fma(a67.y, b1, acc[7][1]);
            }
            __syncthreads();
        }

        const int gn0 = bn + cx;
        float* dst = is_gate ? g_gt[z] : g_cp[z];
        const int ld = is_gate ? DH : DM;
#pragma unroll
        for (int r = 0; r < 8; r++) {
            float2 lo = unpack2(acc[r][0]);
            float2 hi = unpack2(acc[r][1]);
            *(float4*)(&dst[(size_t)(bm + ry + r) * ld + gn0]) =
                make_float4(lo.x, lo.y, hi.x, hi.y);
        }
    } else if (out_W) {   // blocks 192..255: W passthrough (1M floats / 64 blocks)
        size_t base = (size_t)(blockIdx.x - 192) * 16384 + tid * 4;
#pragma unroll 4
        for (int q = 0; q < 16; q++)
            *(float4*)(out_W + base + (size_t)q * 1024) =
                *(const float4*)(W + base + (size_t)q * 1024);
    }
    grid_bar(2);

    // ================= Phase 3: LayerNorm epilogue =================
    {
        const int b = blockIdx.x;
        float h[4];
        float sum = 0.f, sumsq = 0.f;
#pragma unroll
        for (int q = 0; q < 4; q++) {
            int i = tid + q * 256;
            int gi = i & (DH - 1);
            float gpre = bg[gi];
#pragma unroll
            for (int zz = 0; zz < ZC; zz++) gpre += g_gt[zz][(size_t)b * DH + gi];
            float g = 1.f / (1.f + expf(-gpre));
            float cp = 0.f;
#pragma unroll
            for (int zz = 0; zz < ZC; zz++) cp += g_cp[zz][(size_t)b * DM + i];
            float v = fmaf(cp, g, g_phi[(size_t)b * DM + i]);
            h[q] = v;
            sum += v;
            sumsq = fmaf(v, v, sumsq);
        }
#pragma unroll
        for (int o = 16; o > 0; o >>= 1) {
            sum += __shfl_xor_sync(0xFFFFFFFFu, sum, o);
            sumsq += __shfl_xor_sync(0xFFFFFFFFu, sumsq, o);
        }
        int w = tid >> 5, l = tid & 31;
        if (l == 0) { sm.ln.s1[w] = sum; sm.ln.s2[w] = sumsq; }
        __syncthreads();
        if (w == 0) {
            float a = (l < 8) ? sm.ln.s1[l] : 0.f;
            float c = (l < 8) ? sm.ln.s2[l] : 0.f;
#pragma unroll
            for (int o = 4; o > 0; o >>= 1) {
                a += __shfl_xor_sync(0xFFFFFFFFu, a, o);
                c += __shfl_xor_sync(0xFFFFFFFFu, c, o);
            }
            if (l == 0) { sm.ln.s1[0] = a; sm.ln.s2[0] = c; }
        }
        __syncthreads();
        float mu = sm.ln.s1[0] * (1.0f / (float)DM);
        float var = sm.ln.s2[0] * (1.0f / (float)DM) - mu * mu;
        float inv = rsqrtf(var + 1e-5f);
#pragma unroll
        for (int q = 0; q < 4; q++) {
            int i = tid + q * 256;
            out_feat[(size_t)b * DM + i] = (h[q] - mu) * inv * gamma[i] + beta[i];
        }
    }
}

// ============================================================
extern "C" void kernel_launch(void* const* d_in, const int* in_sizes, int n_in,
                              void* d_out, int out_size)
{
    const float* x       = (const float*)d_in[0];
    const float* prev_ca = (const float*)d_in[1];
    const float* Wp      = (const float*)d_in[2];
    const float* bp      = (const float*)d_in[3];
    const float* Wg      = (const float*)d_in[4];
    const float* bg      = (const float*)d_in[5];
    const float* W       = (const float*)d_in[6];
    const float* gamma   = (const float*)d_in[7];
    const float* beta    = (const float*)d_in[8];

    float* out = (float*)d_out;
    const int FEAT = BATCH * DM;
    const int WSZ  = DM * DM;
    float* out_ca = (out_size >= 2 * FEAT) ? out + FEAT : nullptr;
    float* out_W  = (out_size >= 2 * FEAT + WSZ) ? out + 2 * FEAT : nullptr;

    fused_kernel<<<GRID, 256>>>(x, prev_ca, Wp, bp, Wg, bg, W, gamma, beta,
                                out, out_ca, out_W);
}

// round 9
// speedup vs baseline: 1.1947x; 1.1947x over previous
#include <cuda_runtime.h>
#include <math.h>

#define BATCH 256
#define NF 512
#define DM 1024
#define DH 512
#define KH 16          // Fourier harmonics for |cos|
#define ZP 4           // split-K factor for phi
#define ZC 4           // split-K factor for coupled/gate

// -------- scratch --------
__device__ float g_php[ZP][BATCH * DM];   // phi split-K partials
__device__ float g_phi[BATCH * DM];
__device__ float g_ca[BATCH * DM];
__device__ float g_cp[ZC][BATCH * DM];    // coupled split-K partials
__device__ float g_gt[ZC][BATCH * DH];    // gate pre-act split-K partials

typedef unsigned long long u64;

__device__ __forceinline__ u64 f32x2_fma(u64 a, u64 b, u64 c) {
    u64 d;
    asm("fma.rn.f32x2 %0, %1, %2, %3;" : "=l"(d) : "l"(a), "l"(b), "l"(c));
    return d;
}
__device__ __forceinline__ u64 pack_dup(float v) {
    u64 r;
    asm("mov.b64 %0, {%1, %2};" : "=l"(r) : "f"(v), "f"(v));
    return r;
}
__device__ __forceinline__ float2 unpack2(u64 v) {
    float lo, hi;
    asm("mov.b64 {%0, %1}, %2;" : "=f"(lo), "=f"(hi) : "l"(v));
    return make_float2(lo, hi);
}

// ============================================================
// GEMM tiling: BM=64, BN=64, BK=16, 128 threads, 8x4 thread tile,
// DOUBLE-BUFFERED smem with register prefetch (1 sync / ktile).
// ============================================================

#define FMA_TILE(cur)                                                   \
    _Pragma("unroll")                                                   \
    for (int k = 0; k < 16; k++) {                                      \
        ulonglong2 a01 = *(const ulonglong2*)&As[cur][k][ry];           \
        ulonglong2 a23 = *(const ulonglong2*)&As[cur][k][ry + 2];       \
        ulonglong2 a45 = *(const ulonglong2*)&As[cur][k][ry + 4];       \
        ulonglong2 a67 = *(const ulonglong2*)&As[cur][k][ry + 6];       \
        double2 bd = *(const double2*)&Bs[cur][k][cx];                  \
        u64 b0 = __double_as_longlong(bd.x);                            \
        u64 b1 = __double_as_longlong(bd.y);                            \
        acc[0][0] = f32x2_fma(a01.x, b0, acc[0][0]);                    \
        acc[0][1] = f32x2_fma(a01.x, b1, acc[0][1]);                    \
        acc[1][0] = f32x2_fma(a01.y, b0, acc[1][0]);                    \
        acc[1][1] = f32x2_fma(a01.y, b1, acc[1][1]);                    \
        acc[2][0] = f32x2_fma(a23.x, b0, acc[2][0]);                    \
        acc[2][1] = f32x2_fma(a23.x, b1, acc[2][1]);                    \
        acc[3][0] = f32x2_fma(a23.y, b0, acc[3][0]);                    \
        acc[3][1] = f32x2_fma(a23.y, b1, acc[3][1]);                    \
        acc[4][0] = f32x2_fma(a45.x, b0, acc[4][0]);                    \
        acc[4][1] = f32x2_fma(a45.x, b1, acc[4][1]);                    \
        acc[5][0] = f32x2_fma(a45.y, b0, acc[5][0]);                    \
        acc[5][1] = f32x2_fma(a45.y, b1, acc[5][1]);                    \
        acc[6][0] = f32x2_fma(a67.x, b0, acc[6][0]);                    \
        acc[6][1] = f32x2_fma(a67.x, b1, acc[6][1]);                    \
        acc[7][0] = f32x2_fma(a67.y, b0, acc[7][0]);                    \
        acc[7][1] = f32x2_fma(a67.y, b1, acc[7][1]);                    \
    }

#define STORE_A(buf)                                                    \
    As[buf][akh + 0][arow] = pack_dup(pa0.x);                           \
    As[buf][akh + 1][arow] = pack_dup(pa0.y);                           \
    As[buf][akh + 2][arow] = pack_dup(pa0.z);                           \
    As[buf][akh + 3][arow] = pack_dup(pa0.w);                           \
    As[buf][akh + 4][arow] = pack_dup(pa1.x);                           \
    As[buf][akh + 5][arow] = pack_dup(pa1.y);                           \
    As[buf][akh + 6][arow] = pack_dup(pa1.z);                           \
    As[buf][akh + 7][arow] = pack_dup(pa1.w);

#define STORE_B_T(buf)                                                  \
    Bs[buf][akh + 0][arow] = pb0.x; Bs[buf][akh + 1][arow] = pb0.y;     \
    Bs[buf][akh + 2][arow] = pb0.z; Bs[buf][akh + 3][arow] = pb0.w;     \
    Bs[buf][akh + 4][arow] = pb1.x; Bs[buf][akh + 5][arow] = pb1.y;     \
    Bs[buf][akh + 6][arow] = pb1.z; Bs[buf][akh + 7][arow] = pb1.w;

// ---- phi partials: g_php[z] = x @ Wp^T (K-quarter z). grid (16,4,ZP+1) ----
// z == ZP plane: W passthrough copy on otherwise-idle SMs.
__global__ __launch_bounds__(128) void phi_gemm(
    const float* __restrict__ x, const float* __restrict__ Wp,
    const float* __restrict__ W, float* __restrict__ out_W)
{
    __shared__ __align__(16) u64   As[2][16][64];   // 16KB
    __shared__ __align__(16) float Bs[2][16][64];   // 8KB

    const int tid = threadIdx.x;

    if (blockIdx.z == ZP) {      // W copy: 64 blocks x 16384 floats
        if (out_W) {
            int id = blockIdx.y * 16 + blockIdx.x;
            size_t base = (size_t)id * 16384 + tid * 4;
#pragma unroll 8
            for (int q = 0; q < 32; q++)
                *(float4*)(out_W + base + (size_t)q * 512) =
                    *(const float4*)(W + base + (size_t)q * 512);
        }
        return;
    }

    const int bm = blockIdx.y * 64;
    const int bn = blockIdx.x * 64;
    const int z  = blockIdx.z;
    const int ty = tid >> 4, tx = tid & 15;
    const int ry = ty * 8, cx = tx * 4;
    const int arow = tid >> 1, akh = (tid & 1) * 8;

    u64 acc[8][2];
#pragma unroll
    for (int r = 0; r < 8; r++) { acc[r][0] = 0ull; acc[r][1] = 0ull; }

    const int kbeg = z * (NF / ZP);
    const int T = (NF / ZP) / 16;   // 8 ktiles

    const float* asrc = x  + (size_t)(bm + arow) * NF + kbeg + akh;
    const float* bsrc = Wp + (size_t)(bn + arow) * NF + kbeg + akh;

    float4 pa0 = *(const float4*)(asrc);
    float4 pa1 = *(const float4*)(asrc + 4);
    float4 pb0 = *(const float4*)(bsrc);
    float4 pb1 = *(const float4*)(bsrc + 4);
    STORE_A(0); STORE_B_T(0);
    __syncthreads();

    for (int t = 0; t < T; t++) {
        int cur = t & 1;
        if (t + 1 < T) {
            const float* a2 = asrc + (t + 1) * 16;
            const float* b2 = bsrc + (t + 1) * 16;
            pa0 = *(const float4*)(a2);
            pa1 = *(const float4*)(a2 + 4);
            pb0 = *(const float4*)(b2);
            pb1 = *(const float4*)(b2 + 4);
        }
        FMA_TILE(cur);
        if (t + 1 < T) {
            int nxt = cur ^ 1;
            STORE_A(nxt); STORE_B_T(nxt);
        }
        __syncthreads();
    }

    const int gn0 = bn + cx;
#pragma unroll
    for (int r = 0; r < 8; r++) {
        float2 lo = unpack2(acc[r][0]);
        float2 hi = unpack2(acc[r][1]);
        *(float4*)(&g_php[z][(size_t)(bm + ry + r) * DM + gn0]) =
            make_float4(lo.x, lo.y, hi.x, hi.y);
    }
}

// ============================================================
// ca_kernel: one block per batch row. Fourier-harmonic coherence.
// ============================================================
__global__ __launch_bounds__(256) void ca_kernel(
    const float* __restrict__ prev_ca, const float* __restrict__ bp,
    float* __restrict__ out_ca)
{
    __shared__ float red[2 * KH][257];
    __shared__ float shC[KH];
    __shared__ float shS[KH];

    const int b = blockIdx.x;
    const int tid = threadIdx.x;
    const int warp = tid >> 5, lane = tid & 31;
    const int j0 = tid * 4;

    float4 bb = *(const float4*)(bp + j0);
    float phi[4] = { bb.x, bb.y, bb.z, bb.w };
#pragma unroll
    for (int zz = 0; zz < ZP; zz++) {
        float4 p = *(const float4*)(&g_php[zz][(size_t)b * DM + j0]);
        phi[0] += p.x; phi[1] += p.y; phi[2] += p.z; phi[3] += p.w;
    }
    *(float4*)(&g_phi[(size_t)b * DM + j0]) =
        make_float4(phi[0], phi[1], phi[2], phi[3]);

    float c1[4], s1[4], t[4], ck[4], sk[4], cm[4], sm[4];
#pragma unroll
    for (int q = 0; q < 4; q++) {
        sincosf(2.0f * phi[q], &s1[q], &c1[q]);
        t[q] = 2.0f * c1[q];
        ck[q] = c1[q]; sk[q] = s1[q];
        cm[q] = 1.0f;  sm[q] = 0.0f;
    }

#pragma unroll
    for (int k = 0; k < KH; k++) {
        red[k][tid]      = ck[0] + ck[1] + ck[2] + ck[3];
        red[k + KH][tid] = sk[0] + sk[1] + sk[2] + sk[3];
#pragma unroll
        for (int q = 0; q < 4; q++) {
            float cn = fmaf(t[q], ck[q], -cm[q]);
            float sn = fmaf(t[q], sk[q], -sm[q]);
            cm[q] = ck[q]; ck[q] = cn;
            sm[q] = sk[q]; sk[q] = sn;
        }
    }
    __syncthreads();

#pragma unroll
    for (int h = 0; h < 4; h++) {
        int hh = warp * 4 + h;
        float v = red[hh][lane] + red[hh][lane + 32] +
                  red[hh][lane + 64] + red[hh][lane + 96] +
                  red[hh][lane + 128] + red[hh][lane + 160] +
                  red[hh][lane + 192] + red[hh][lane + 224];
#pragma unroll
        for (int o = 16; o > 0; o >>= 1)
            v += __shfl_xor_sync(0xFFFFFFFFu, v, o);
        if (lane == 0) {
            int m = (hh & (KH - 1)) + 1;
            float coef = ((m & 1) ? 1.0f : -1.0f) *
                         (4.0f / 3.14159265358979f) / (float)(4 * m * m - 1) *
                         (1.0f / (float)DM);
            if (hh < KH) shC[hh] = v * coef;
            else         shS[hh - KH] = v * coef;
        }
    }
    __syncthreads();

    float acc[4] = { 0.63661977f, 0.63661977f, 0.63661977f, 0.63661977f };
#pragma unroll
    for (int q = 0; q < 4; q++) {
        ck[q] = c1[q]; sk[q] = s1[q];
        cm[q] = 1.0f;  sm[q] = 0.0f;
    }
#pragma unroll
    for (int k = 0; k < KH; k++) {
        float C = shC[k], S = shS[k];
#pragma unroll
        for (int q = 0; q < 4; q++) {
            acc[q] = fmaf(ck[q], C, acc[q]);
            acc[q] = fmaf(sk[q], S, acc[q]);
            float cn = fmaf(t[q], ck[q], -cm[q]);
            float sn = fmaf(t[q], sk[q], -sm[q]);
            cm[q] = ck[q]; ck[q] = cn;
            sm[q] = sk[q]; sk[q] = sn;
        }
    }

    float4 pc = *(const float4*)(prev_ca + (size_t)b * DM + j0);
    float4 ca;
    ca.x = pc.x * 0.95f + acc[0] * 0.05f;
    ca.y = pc.y * 0.95f + acc[1] * 0.05f;
    ca.z = pc.z * 0.95f + acc[2] * 0.05f;
    ca.w = pc.w * 0.95f + acc[3] * 0.05f;
    *(float4*)(&g_ca[(size_t)b * DM + j0]) = ca;
    if (out_ca) *(float4*)(out_ca + (size_t)b * DM + j0) = ca;
}

// ============================================================
// merged split-K GEMM: coupled = phi@W (NN, bx<16), gate-preact =
// ca@Wg^T (NT, bx>=16). grid (24, 4, ZC), 128 threads, 8x4 tile,
// double-buffered + prefetch.
// ============================================================
__global__ __launch_bounds__(128) void coupled_gate_gemm(
    const float* __restrict__ W, const float* __restrict__ Wg)
{
    __shared__ __align__(16) u64   As[2][16][64];
    __shared__ __align__(16) float Bs[2][16][64];

    const bool is_gate = (blockIdx.x >= 16);
    const int bm = blockIdx.y * 64;
    const int bn = (is_gate ? (blockIdx.x - 16) : blockIdx.x) * 64;
    const int z  = blockIdx.z;
    const int tid = threadIdx.x;
    const int ty = tid >> 4, tx = tid & 15;
    const int ry = ty * 8, cx = tx * 4;
    const int arow = tid >> 1, akh = (tid & 1) * 8;

    const float* Ap = is_gate ? (const float*)g_ca : (const float*)g_phi;

    u64 acc[8][2];
#pragma unroll
    for (int r = 0; r < 8; r++) { acc[r][0] = 0ull; acc[r][1] = 0ull; }

    const int kbeg = z * (DM / ZC);
    const int T = (DM / ZC) / 16;   // 16 ktiles

    const float* asrc = Ap + (size_t)(bm + arow) * DM + kbeg + akh;
    const float* bsrcT = Wg + (size_t)(bn + arow) * DM + kbeg + akh;
    const int kr = tid >> 3, nc = (tid & 7) << 3;
    const float* bsrcN = W + (size_t)(kbeg + kr) * DM + bn + nc;

    float4 pa0 = *(const float4*)(asrc);
    float4 pa1 = *(const float4*)(asrc + 4);
    float4 pb0, pb1;
    if (is_gate) {
        pb0 = *(const float4*)(bsrcT);
        pb1 = *(const float4*)(bsrcT + 4);
    } else {
        pb0 = *(const float4*)(bsrcN);
        pb1 = *(const float4*)(bsrcN + 4);
    }
    STORE_A(0);
    if (is_gate) { STORE_B_T(0); }
    else {
        *(float4*)&Bs[0][kr][nc]     = pb0;
        *(float4*)&Bs[0][kr][nc + 4] = pb1;
    }
    __syncthreads();

    for (int t = 0; t < T; t++) {
        int cur = t & 1;
        if (t + 1 < T) {
            const float* a2 = asrc + (t + 1) * 16;
            pa0 = *(const float4*)(a2);
            pa1 = *(const float4*)(a2 + 4);
            if (is_gate) {
                const float* b2 = bsrcT + (t + 1) * 16;
                pb0 = *(const float4*)(b2);
                pb1 = *(const float4*)(b2 + 4);
            } else {
                const float* b2 = bsrcN + (size_t)(t + 1) * 16 * DM;
                pb0 = *(const float4*)(b2);
                pb1 = *(const float4*)(b2 + 4);
            }
        }
        FMA_TILE(cur);
        if (t + 1 < T) {
            int nxt = cur ^ 1;
            STORE_A(nxt);
            if (is_gate) { STORE_B_T(nxt); }
            else {
                *(float4*)&Bs[nxt][kr][nc]     = pb0;
                *(float4*)&Bs[nxt][kr][nc + 4] = pb1;
            }
        }
        __syncthreads();
    }

    const int gn0 = bn + cx;
    float* dst = is_gate ? g_gt[z] : g_cp[z];
    const int ld = is_gate ? DH : DM;
#pragma unroll
    for (int r = 0; r < 8; r++) {
        float2 lo = unpack2(acc[r][0]);
        float2 hi = unpack2(acc[r][1]);
        *(float4*)(&dst[(size_t)(bm + ry + r) * ld + gn0]) =
            make_float4(lo.x, lo.y, hi.x, hi.y);
    }
}

// ============================================================
// features = LN( Σcp * sigmoid(Σgt+bg)[tiled] + phi )
// 512 threads/block, float2 per thread (elements 2t, 2t+1);
// gate index pairs are shared across the two halves of the row.
// ============================================================
__global__ __launch_bounds__(512) void fuse_ln_kernel(
    const float* __restrict__ bg,
    const float* __restrict__ gamma, const float* __restrict__ beta,
    float* __restrict__ out_feat)
{
    const int tid = threadIdx.x;
    const int b = blockIdx.x;
    __shared__ float s1[16], s2[16];

    const int i = tid * 2;               // element pair in row
    const int gi = i & (DH - 1);         // gate pair index

    float2 gp = *(const float2*)(bg + gi);
#pragma unroll
    for (int zz = 0; zz < ZC; zz++) {
        float2 g2 = *(const float2*)(&g_gt[zz][(size_t)b * DH + gi]);
        gp.x += g2.x; gp.y += g2.y;
    }
    float gx = 1.f / (1.f + expf(-gp.x));
    float gy = 1.f / (1.f + expf(-gp.y));

    float2 cp = make_float2(0.f, 0.f);
#pragma unroll
    for (int zz = 0; zz < ZC; zz++) {
        float2 c2 = *(const float2*)(&g_cp[zz][(size_t)b * DM + i]);
        cp.x += c2.x; cp.y += c2.y;
    }
    float2 ph = *(const float2*)(&g_phi[(size_t)b * DM + i]);
    float hx = fmaf(cp.x, gx, ph.x);
    float hy = fmaf(cp.y, gy, ph.y);

    float sum = hx + hy;
    float sumsq = fmaf(hx, hx, hy * hy);
#pragma unroll
    for (int o = 16; o > 0; o >>= 1) {
        sum += __shfl_xor_sync(0xFFFFFFFFu, sum, o);
        sumsq += __shfl_xor_sync(0xFFFFFFFFu, sumsq, o);
    }
    int w = tid >> 5, l = tid & 31;
    if (l == 0) { s1[w] = sum; s2[w] = sumsq; }
    __syncthreads();
    if (w == 0) {
        float a = (l < 16) ? s1[l] : 0.f;
        float c = (l < 16) ? s2[l] : 0.f;
#pragma unroll
        for (int o = 8; o > 0; o >>= 1) {
            a += __shfl_xor_sync(0xFFFFFFFFu, a, o);
            c += __shfl_xor_sync(0xFFFFFFFFu, c, o);
        }
        if (l == 0) { s1[0] = a; s2[0] = c; }
    }
    __syncthreads();
    float mu = s1[0] * (1.0f / (float)DM);
    float var = s2[0] * (1.0f / (float)DM) - mu * mu;
    float inv = rsqrtf(var + 1e-5f);

    float2 gm = *(const float2*)(gamma + i);
    float2 bt = *(const float2*)(beta + i);
    float2 o;
    o.x = (hx - mu) * inv * gm.x + bt.x;
    o.y = (hy - mu) * inv * gm.y + bt.y;
    *(float2*)(out_feat + (size_t)b * DM + i) = o;
}

// ============================================================
extern "C" void kernel_launch(void* const* d_in, const int* in_sizes, int n_in,
                              void* d_out, int out_size)
{
    const float* x       = (const float*)d_in[0];
    const float* prev_ca = (const float*)d_in[1];
    const float* Wp      = (const float*)d_in[2];
    const float* bp      = (const float*)d_in[3];
    const float* Wg      = (const float*)d_in[4];
    const float* bg      = (const float*)d_in[5];
    const float* W       = (const float*)d_in[6];
    const float* gamma   = (const float*)d_in[7];
    const float* beta    = (const float*)d_in[8];

    float* out = (float*)d_out;
    const int FEAT = BATCH * DM;
    const int WSZ  = DM * DM;
    float* out_ca = (out_size >= 2 * FEAT) ? out + FEAT : nullptr;
    float* out_W  = (out_size >= 2 * FEAT + WSZ) ? out + 2 * FEAT : nullptr;

    // phi partials (split-K x4, double-buffered) + W copy plane: 320 blocks
    phi_gemm<<<dim3(DM / 64, BATCH / 64, ZP + 1), 128>>>(x, Wp, W, out_W);

    // phi combine + Fourier coherence + ca: 256 blocks
    ca_kernel<<<BATCH, 256>>>(prev_ca, bp, out_ca);

    // coupled + gate pre-act (split-K x4, double-buffered): 384 blocks
    coupled_gate_gemm<<<dim3(DM / 64 + DH / 64, BATCH / 64, ZC), 128>>>(W, Wg);

    // LN epilogue: 256 blocks x 512 threads
    fuse_ln_kernel<<<BATCH, 512>>>(bg, gamma, beta, out);
}